// round 1
// baseline (speedup 1.0000x reference)
#include <cuda_runtime.h>

// Problem constants
#define B_ 4
#define S_ 2048
#define D_ 1024
#define H_ 16
#define DK_ 64
#define M_ (B_ * S_)   // 8192 rows

// Scratch (device globals — no allocation allowed)
__device__ float g_q[(long long)M_ * D_];  // [B,H,S,DK]
__device__ float g_k[(long long)M_ * D_];  // [B,H,S,DK]
__device__ float g_v[(long long)M_ * D_];  // [B,H,S,DK]
__device__ float g_x[(long long)M_ * D_];  // [B,S,D] attention output

// ---------------------------------------------------------------------------
// Tiled fp32 GEMM: out[m,n] = sum_k X[m,k] * W[n,k] + bias[n]
// BM=BN=128, BK=8, 256 threads, 8x8 per thread.
// SPLIT=true writes head-split layout [B,H,S,DK]; else row-major [M,D].
// ---------------------------------------------------------------------------
template <bool SPLIT>
__device__ __forceinline__ void gemm_body(
    float* As, float* Bs,
    const float* __restrict__ X, const float* __restrict__ W,
    const float* __restrict__ bias, float* __restrict__ out)
{
    const int tid = threadIdx.x;
    const int m0 = blockIdx.y * 128;
    const int n0 = blockIdx.x * 128;
    const int tr = tid >> 4;          // 0..15 (rows)
    const int tc = tid & 15;          // 0..15 (cols)
    const int lrow = tid >> 1;        // 0..127
    const int lseg = (tid & 1) * 4;   // 0 or 4

    float acc[8][8];
#pragma unroll
    for (int i = 0; i < 8; i++)
#pragma unroll
        for (int j = 0; j < 8; j++) acc[i][j] = 0.0f;

    const float* ap = X + (long long)(m0 + lrow) * D_ + lseg;
    const float* bp = W + (long long)(n0 + lrow) * D_ + lseg;

    for (int k0 = 0; k0 < D_; k0 += 8) {
        float4 av = *(const float4*)(ap + k0);
        float4 bv = *(const float4*)(bp + k0);
        __syncthreads();
        As[(lseg + 0) * 132 + lrow] = av.x;
        As[(lseg + 1) * 132 + lrow] = av.y;
        As[(lseg + 2) * 132 + lrow] = av.z;
        As[(lseg + 3) * 132 + lrow] = av.w;
        Bs[(lseg + 0) * 132 + lrow] = bv.x;
        Bs[(lseg + 1) * 132 + lrow] = bv.y;
        Bs[(lseg + 2) * 132 + lrow] = bv.z;
        Bs[(lseg + 3) * 132 + lrow] = bv.w;
        __syncthreads();
#pragma unroll
        for (int kk = 0; kk < 8; kk++) {
            float4 a0 = *(const float4*)&As[kk * 132 + tr * 8];
            float4 a1 = *(const float4*)&As[kk * 132 + tr * 8 + 4];
            float4 b0 = *(const float4*)&Bs[kk * 132 + tc * 8];
            float4 b1 = *(const float4*)&Bs[kk * 132 + tc * 8 + 4];
            float a[8] = {a0.x, a0.y, a0.z, a0.w, a1.x, a1.y, a1.z, a1.w};
            float b[8] = {b0.x, b0.y, b0.z, b0.w, b1.x, b1.y, b1.z, b1.w};
#pragma unroll
            for (int i = 0; i < 8; i++)
#pragma unroll
                for (int j = 0; j < 8; j++) acc[i][j] = fmaf(a[i], b[j], acc[i][j]);
        }
    }

#pragma unroll
    for (int i = 0; i < 8; i++) {
        const int m = m0 + tr * 8 + i;
#pragma unroll
        for (int j = 0; j < 8; j += 4) {
            const int n = n0 + tc * 8 + j;
            float4 r;
            r.x = acc[i][j + 0] + bias[n + 0];
            r.y = acc[i][j + 1] + bias[n + 1];
            r.z = acc[i][j + 2] + bias[n + 2];
            r.w = acc[i][j + 3] + bias[n + 3];
            if (SPLIT) {
                const int bb = m >> 11;           // m / S_
                const int ss = m & (S_ - 1);
                const int h = n >> 6;             // n / DK_
                const int dk = n & (DK_ - 1);
                *(float4*)&out[(((long long)bb * H_ + h) * S_ + ss) * DK_ + dk] = r;
            } else {
                *(float4*)&out[(long long)m * D_ + n] = r;
            }
        }
    }
}

__global__ __launch_bounds__(256) void qkv_kernel(
    const float* __restrict__ q, const float* __restrict__ k, const float* __restrict__ v,
    const float* __restrict__ wq, const float* __restrict__ bq,
    const float* __restrict__ wk, const float* __restrict__ bk,
    const float* __restrict__ wv, const float* __restrict__ bv)
{
    __shared__ __align__(16) float As[8 * 132];
    __shared__ __align__(16) float Bs[8 * 132];
    if (blockIdx.z == 0)      gemm_body<true>(As, Bs, q, wq, bq, g_q);
    else if (blockIdx.z == 1) gemm_body<true>(As, Bs, k, wk, bk, g_k);
    else                      gemm_body<true>(As, Bs, v, wv, bv, g_v);
}

__global__ __launch_bounds__(256) void oproj_kernel(
    const float* __restrict__ wo, const float* __restrict__ bo, float* __restrict__ out)
{
    __shared__ __align__(16) float As[8 * 132];
    __shared__ __align__(16) float Bs[8 * 132];
    gemm_body<false>(As, Bs, g_x, wo, bo, out);
}

// ---------------------------------------------------------------------------
// Flash-style attention, fp32. One block = one (b,h) and 64 q-rows.
// 256 threads, thread (ty,tx) owns a 4x4 microtile of S and of O.
// Smem: Qs/Ks transposed [dk][row] with pad 68; Vs [j][dk] 64; Ps [i][j] 64.
// ---------------------------------------------------------------------------
#define QS_OFF 0
#define KS_OFF (64 * 68)
#define VS_OFF (2 * 64 * 68)
#define PS_OFF (2 * 64 * 68 + 64 * 64)
#define ATTN_SMEM_FLOATS (2 * 64 * 68 + 2 * 64 * 64)

__global__ __launch_bounds__(256) void attn_kernel(const int* __restrict__ mask)
{
    extern __shared__ __align__(16) float sm[];
    float* Qs = sm + QS_OFF;
    float* Ks = sm + KS_OFF;
    float* Vs = sm + VS_OFF;
    float* Ps = sm + PS_OFF;

    const int tid = threadIdx.x;
    const int ty = tid >> 4;   // 0..15
    const int tx = tid & 15;   // 0..15
    const int q0 = blockIdx.x * 64;
    const int bh = blockIdx.y;

    const float* Qg = g_q + (long long)bh * S_ * DK_;
    const float* Kg = g_k + (long long)bh * S_ * DK_;
    const float* Vg = g_v + (long long)bh * S_ * DK_;

    // Load Q tile transposed into smem (scaled by 1/sqrt(DK)=0.125)
    {
        const int seg = tid & 15;   // dk segment (4 floats)
        const int rg = tid >> 4;    // row group (4 rows)
        const float* p = Qg + (long long)(q0 + rg * 4) * DK_ + seg * 4;
        float4 r0 = *(const float4*)(p);
        float4 r1 = *(const float4*)(p + DK_);
        float4 r2 = *(const float4*)(p + 2 * DK_);
        float4 r3 = *(const float4*)(p + 3 * DK_);
        const float sc = 0.125f;
        float* dst = Qs + (seg * 4) * 68 + rg * 4;
        *(float4*)(dst + 0 * 68) = make_float4(r0.x * sc, r1.x * sc, r2.x * sc, r3.x * sc);
        *(float4*)(dst + 1 * 68) = make_float4(r0.y * sc, r1.y * sc, r2.y * sc, r3.y * sc);
        *(float4*)(dst + 2 * 68) = make_float4(r0.z * sc, r1.z * sc, r2.z * sc, r3.z * sc);
        *(float4*)(dst + 3 * 68) = make_float4(r0.w * sc, r1.w * sc, r2.w * sc, r3.w * sc);
    }

    float m_i[4], l_i[4], acc[4][4];
#pragma unroll
    for (int i = 0; i < 4; i++) {
        m_i[i] = -1e30f;
        l_i[i] = 0.0f;
#pragma unroll
        for (int j = 0; j < 4; j++) acc[i][j] = 0.0f;
    }

    for (int kt = 0; kt < S_ / 64; kt++) {
        const int k0 = kt * 64;
        __syncthreads();  // previous iteration fully consumed smem (also covers Q load on iter 0)

        // Load K tile transposed + V tile natural
        {
            const int seg = tid & 15;
            const int rg = tid >> 4;
            const float* pk = Kg + (long long)(k0 + rg * 4) * DK_ + seg * 4;
            float4 k0v = *(const float4*)(pk);
            float4 k1v = *(const float4*)(pk + DK_);
            float4 k2v = *(const float4*)(pk + 2 * DK_);
            float4 k3v = *(const float4*)(pk + 3 * DK_);
            float* kd = Ks + (seg * 4) * 68 + rg * 4;
            *(float4*)(kd + 0 * 68) = make_float4(k0v.x, k1v.x, k2v.x, k3v.x);
            *(float4*)(kd + 1 * 68) = make_float4(k0v.y, k1v.y, k2v.y, k3v.y);
            *(float4*)(kd + 2 * 68) = make_float4(k0v.z, k1v.z, k2v.z, k3v.z);
            *(float4*)(kd + 3 * 68) = make_float4(k0v.w, k1v.w, k2v.w, k3v.w);

            const float* pv = Vg + (long long)(k0 + rg * 4) * DK_ + seg * 4;
            *(float4*)&Vs[(rg * 4 + 0) * 64 + seg * 4] = *(const float4*)(pv);
            *(float4*)&Vs[(rg * 4 + 1) * 64 + seg * 4] = *(const float4*)(pv + DK_);
            *(float4*)&Vs[(rg * 4 + 2) * 64 + seg * 4] = *(const float4*)(pv + 2 * DK_);
            *(float4*)&Vs[(rg * 4 + 3) * 64 + seg * 4] = *(const float4*)(pv + 3 * DK_);
        }
        __syncthreads();

        // S = (Q/8) @ K^T   (4x4 per thread)
        float s[4][4];
#pragma unroll
        for (int i = 0; i < 4; i++)
#pragma unroll
            for (int j = 0; j < 4; j++) s[i][j] = 0.0f;

#pragma unroll 8
        for (int kk = 0; kk < 64; kk++) {
            float4 qa = *(const float4*)&Qs[kk * 68 + ty * 4];
            float4 ka = *(const float4*)&Ks[kk * 68 + tx * 4];
            float a[4] = {qa.x, qa.y, qa.z, qa.w};
            float b[4] = {ka.x, ka.y, ka.z, ka.w};
#pragma unroll
            for (int i = 0; i < 4; i++)
#pragma unroll
                for (int j = 0; j < 4; j++) s[i][j] = fmaf(a[i], b[j], s[i][j]);
        }

        // Apply mask (mask==0 -> -1e9, matches reference)
#pragma unroll
        for (int ii = 0; ii < 4; ii++) {
            const int4 mv = *(const int4*)&mask[(long long)(q0 + ty * 4 + ii) * S_ + k0 + tx * 4];
            if (mv.x == 0) s[ii][0] = -1e9f;
            if (mv.y == 0) s[ii][1] = -1e9f;
            if (mv.z == 0) s[ii][2] = -1e9f;
            if (mv.w == 0) s[ii][3] = -1e9f;
        }

        // Online softmax update per row (row reduction across the 16 tx lanes)
#pragma unroll
        for (int ii = 0; ii < 4; ii++) {
            float mx = fmaxf(fmaxf(s[ii][0], s[ii][1]), fmaxf(s[ii][2], s[ii][3]));
            mx = fmaxf(mx, __shfl_xor_sync(0xffffffffu, mx, 1));
            mx = fmaxf(mx, __shfl_xor_sync(0xffffffffu, mx, 2));
            mx = fmaxf(mx, __shfl_xor_sync(0xffffffffu, mx, 4));
            mx = fmaxf(mx, __shfl_xor_sync(0xffffffffu, mx, 8));
            const float mnew = fmaxf(m_i[ii], mx);
            const float al = __expf(m_i[ii] - mnew);
            float p0 = __expf(s[ii][0] - mnew);
            float p1 = __expf(s[ii][1] - mnew);
            float p2 = __expf(s[ii][2] - mnew);
            float p3 = __expf(s[ii][3] - mnew);
            float sum = (p0 + p1) + (p2 + p3);
            sum += __shfl_xor_sync(0xffffffffu, sum, 1);
            sum += __shfl_xor_sync(0xffffffffu, sum, 2);
            sum += __shfl_xor_sync(0xffffffffu, sum, 4);
            sum += __shfl_xor_sync(0xffffffffu, sum, 8);
            l_i[ii] = l_i[ii] * al + sum;
            m_i[ii] = mnew;
            acc[ii][0] *= al;
            acc[ii][1] *= al;
            acc[ii][2] *= al;
            acc[ii][3] *= al;
            *(float4*)&Ps[(ty * 4 + ii) * 64 + tx * 4] = make_float4(p0, p1, p2, p3);
        }
        __syncthreads();

        // O += P @ V  (4x4 per thread; P read as scalar broadcast)
#pragma unroll 8
        for (int j = 0; j < 64; j++) {
            float4 vv = *(const float4*)&Vs[j * 64 + tx * 4];
            float p0 = Ps[(ty * 4 + 0) * 64 + j];
            float p1 = Ps[(ty * 4 + 1) * 64 + j];
            float p2 = Ps[(ty * 4 + 2) * 64 + j];
            float p3 = Ps[(ty * 4 + 3) * 64 + j];
            acc[0][0] = fmaf(p0, vv.x, acc[0][0]);
            acc[0][1] = fmaf(p0, vv.y, acc[0][1]);
            acc[0][2] = fmaf(p0, vv.z, acc[0][2]);
            acc[0][3] = fmaf(p0, vv.w, acc[0][3]);
            acc[1][0] = fmaf(p1, vv.x, acc[1][0]);
            acc[1][1] = fmaf(p1, vv.y, acc[1][1]);
            acc[1][2] = fmaf(p1, vv.z, acc[1][2]);
            acc[1][3] = fmaf(p1, vv.w, acc[1][3]);
            acc[2][0] = fmaf(p2, vv.x, acc[2][0]);
            acc[2][1] = fmaf(p2, vv.y, acc[2][1]);
            acc[2][2] = fmaf(p2, vv.z, acc[2][2]);
            acc[2][3] = fmaf(p2, vv.w, acc[2][3]);
            acc[3][0] = fmaf(p3, vv.x, acc[3][0]);
            acc[3][1] = fmaf(p3, vv.y, acc[3][1]);
            acc[3][2] = fmaf(p3, vv.z, acc[3][2]);
            acc[3][3] = fmaf(p3, vv.w, acc[3][3]);
        }
    }

    // Normalize and store to [B,S,D] layout
    const int bb = bh >> 4;
    const int h = bh & 15;
#pragma unroll
    for (int ii = 0; ii < 4; ii++) {
        const float inv = 1.0f / l_i[ii];
        float4 r = make_float4(acc[ii][0] * inv, acc[ii][1] * inv,
                               acc[ii][2] * inv, acc[ii][3] * inv);
        const long long row =
            (long long)(bb * S_ + q0 + ty * 4 + ii) * D_ + h * DK_ + tx * 4;
        *(float4*)&g_x[row] = r;
    }
}

// ---------------------------------------------------------------------------
extern "C" void kernel_launch(void* const* d_in, const int* in_sizes, int n_in,
                              void* d_out, int out_size)
{
    (void)in_sizes; (void)n_in; (void)out_size;
    const float* q    = (const float*)d_in[0];
    const float* k    = (const float*)d_in[1];
    const float* v    = (const float*)d_in[2];
    const int*   mask = (const int*)d_in[3];
    const float* wq   = (const float*)d_in[4];
    const float* bq   = (const float*)d_in[5];
    const float* wk   = (const float*)d_in[6];
    const float* bk   = (const float*)d_in[7];
    const float* wv   = (const float*)d_in[8];
    const float* bv   = (const float*)d_in[9];
    const float* wo   = (const float*)d_in[10];
    const float* bo   = (const float*)d_in[11];
    float* out = (float*)d_out;

    // QKV projections (fused launch, z selects projection)
    dim3 gqkv(D_ / 128, M_ / 128, 3);
    qkv_kernel<<<gqkv, 256>>>(q, k, v, wq, bq, wk, bk, wv, bv);

    // Attention
    const size_t smem_bytes = (size_t)ATTN_SMEM_FLOATS * sizeof(float);
    cudaFuncSetAttribute(attn_kernel, cudaFuncAttributeMaxDynamicSharedMemorySize,
                         (int)smem_bytes);
    dim3 gattn(S_ / 64, B_ * H_);
    attn_kernel<<<gattn, 256, smem_bytes>>>(mask);

    // Output projection
    dim3 gop(D_ / 128, M_ / 128);
    oproj_kernel<<<gop, 256>>>(wo, bo, out);
}

// round 2
// speedup vs baseline: 2.6431x; 2.6431x over previous
#include <cuda_runtime.h>
#include <cstdint>

#define B_ 4
#define S_ 2048
#define D_ 1024
#define H_ 16
#define DK_ 64
#define M_ (B_ * S_)   // 8192

// Scratch (device globals — no allocation allowed)
__device__ float g_q[M_ * D_];   // [B,H,S,DK], tf32-rounded, q pre-scaled by 1/8
__device__ float g_k[M_ * D_];   // [B,H,S,DK], tf32-rounded
__device__ float g_v[M_ * D_];   // [B,H,S,DK], tf32-rounded
__device__ float g_x[M_ * D_];   // [B,S,D] attention output (fp32)
__device__ int   g_mflag[16 * 32]; // per (128-q-tile, 64-k-tile): 1 = all mask bits set

__device__ __forceinline__ float to_tf32(float x) {
    float r;
    asm("cvt.rna.tf32.f32 %0, %1;" : "=f"(r) : "f"(x));
    return r;
}

__device__ __forceinline__ void mma8(float c[4], float a0, float a1, float a2, float a3,
                                     float b0, float b1) {
    asm volatile(
        "mma.sync.aligned.m16n8k8.row.col.f32.tf32.tf32.f32 "
        "{%0,%1,%2,%3}, {%4,%5,%6,%7}, {%8,%9}, {%0,%1,%2,%3};"
        : "+f"(c[0]), "+f"(c[1]), "+f"(c[2]), "+f"(c[3])
        : "r"(__float_as_uint(a0)), "r"(__float_as_uint(a1)),
          "r"(__float_as_uint(a2)), "r"(__float_as_uint(a3)),
          "r"(__float_as_uint(b0)), "r"(__float_as_uint(b1)));
}

// ---------------------------------------------------------------------------
// tf32 tensor-core GEMM: out[m,n] = sum_k X[m,k]*W[n,k] + bias[n]
// BM=BN=128, BK=16, 256 threads = 8 warps (4m x 2n), warp tile 32x64.
// Smem row-major [row][20] (stride 20 => conflict-free fragment loads).
// ---------------------------------------------------------------------------
template <bool SPLIT>
__device__ __forceinline__ void gemm_tc(
    float* As, float* Bs,
    const float* __restrict__ X, const float* __restrict__ W,
    const float* __restrict__ bias, float* __restrict__ out, float scale)
{
    const int tid = threadIdx.x;
    const int lane = tid & 31, wid = tid >> 5;
    const int g = lane >> 2, tg = lane & 3;
    const int wm = wid >> 1, wn = wid & 1;
    const int m0 = blockIdx.y * 128, n0 = blockIdx.x * 128;

    // global loaders: 2 rows of A, 2 rows of B per thread, 4 consecutive floats
    const int lr = tid >> 2;          // 0..63
    const int ls = (tid & 3) * 4;     // 0,4,8,12
    const float* xa = X + (m0 + lr) * D_ + ls;
    const float* xb = X + (m0 + lr + 64) * D_ + ls;
    const float* wa = W + (n0 + lr) * D_ + ls;
    const float* wb = W + (n0 + lr + 64) * D_ + ls;

    float acc[2][8][4];
#pragma unroll
    for (int mt = 0; mt < 2; mt++)
#pragma unroll
        for (int nt = 0; nt < 8; nt++)
#pragma unroll
            for (int i = 0; i < 4; i++) acc[mt][nt][i] = 0.0f;

    float4 pa0 = *(const float4*)xa;
    float4 pa1 = *(const float4*)xb;
    float4 pb0 = *(const float4*)wa;
    float4 pb1 = *(const float4*)wb;

    for (int k0 = 0; k0 < D_; k0 += 16) {
        __syncthreads();
        *(float4*)&As[lr * 20 + ls] =
            make_float4(to_tf32(pa0.x), to_tf32(pa0.y), to_tf32(pa0.z), to_tf32(pa0.w));
        *(float4*)&As[(lr + 64) * 20 + ls] =
            make_float4(to_tf32(pa1.x), to_tf32(pa1.y), to_tf32(pa1.z), to_tf32(pa1.w));
        *(float4*)&Bs[lr * 20 + ls] =
            make_float4(to_tf32(pb0.x), to_tf32(pb0.y), to_tf32(pb0.z), to_tf32(pb0.w));
        *(float4*)&Bs[(lr + 64) * 20 + ls] =
            make_float4(to_tf32(pb1.x), to_tf32(pb1.y), to_tf32(pb1.z), to_tf32(pb1.w));
        __syncthreads();
        if (k0 + 16 < D_) {
            pa0 = *(const float4*)(xa + k0 + 16);
            pa1 = *(const float4*)(xb + k0 + 16);
            pb0 = *(const float4*)(wa + k0 + 16);
            pb1 = *(const float4*)(wb + k0 + 16);
        }
#pragma unroll
        for (int kk = 0; kk < 2; kk++) {
            const int kb = kk * 8 + tg;
            float a[2][4];
#pragma unroll
            for (int mt = 0; mt < 2; mt++) {
                const float* Ap = &As[(wm * 32 + mt * 16 + g) * 20 + kb];
                a[mt][0] = Ap[0];
                a[mt][2] = Ap[4];
                a[mt][1] = Ap[8 * 20];
                a[mt][3] = Ap[8 * 20 + 4];
            }
#pragma unroll
            for (int nt = 0; nt < 8; nt++) {
                const float* Bp = &Bs[(wn * 64 + nt * 8 + g) * 20 + kb];
                const float b0 = Bp[0], b1 = Bp[4];
                mma8(acc[0][nt], a[0][0], a[0][1], a[0][2], a[0][3], b0, b1);
                mma8(acc[1][nt], a[1][0], a[1][1], a[1][2], a[1][3], b0, b1);
            }
        }
    }

    // epilogue
#pragma unroll
    for (int mt = 0; mt < 2; mt++) {
        const int r0 = m0 + wm * 32 + mt * 16 + g;
#pragma unroll
        for (int nt = 0; nt < 8; nt++) {
            const int c = n0 + wn * 64 + nt * 8 + tg * 2;
            const float bv0 = bias[c], bv1 = bias[c + 1];
            float v00 = acc[mt][nt][0] + bv0, v01 = acc[mt][nt][1] + bv1;
            float v10 = acc[mt][nt][2] + bv0, v11 = acc[mt][nt][3] + bv1;
            if (SPLIT) {
                v00 = to_tf32(v00 * scale); v01 = to_tf32(v01 * scale);
                v10 = to_tf32(v10 * scale); v11 = to_tf32(v11 * scale);
                const int h = c >> 6, dk = c & 63;
                const int bb = r0 >> 11, ss = r0 & 2047;
                float* o0 = &out[(((bb * H_ + h) * S_) + ss) * DK_ + dk];
                *(float2*)o0 = make_float2(v00, v01);
                *(float2*)(o0 + 8 * DK_) = make_float2(v10, v11);
            } else {
                *(float2*)&out[r0 * D_ + c] = make_float2(v00, v01);
                *(float2*)&out[(r0 + 8) * D_ + c] = make_float2(v10, v11);
            }
        }
    }
}

__global__ __launch_bounds__(256) void qkv_kernel(
    const float* __restrict__ q, const float* __restrict__ k, const float* __restrict__ v,
    const float* __restrict__ wq, const float* __restrict__ bq,
    const float* __restrict__ wk, const float* __restrict__ bk,
    const float* __restrict__ wv, const float* __restrict__ bv)
{
    __shared__ __align__(16) float As[128 * 20];
    __shared__ __align__(16) float Bs[128 * 20];
    if (blockIdx.z == 0)      gemm_tc<true>(As, Bs, q, wq, bq, g_q, 0.125f);
    else if (blockIdx.z == 1) gemm_tc<true>(As, Bs, k, wk, bk, g_k, 1.0f);
    else                      gemm_tc<true>(As, Bs, v, wv, bv, g_v, 1.0f);
}

__global__ __launch_bounds__(256) void oproj_kernel(
    const float* __restrict__ wo, const float* __restrict__ bo, float* __restrict__ out)
{
    __shared__ __align__(16) float As[128 * 20];
    __shared__ __align__(16) float Bs[128 * 20];
    gemm_tc<false>(As, Bs, g_x, wo, bo, out, 1.0f);
}

// ---------------------------------------------------------------------------
// Mask prescan: flag[qt][kt] = 1 iff mask is all-nonzero in the 128x64 tile.
// ---------------------------------------------------------------------------
__global__ __launch_bounds__(256) void mask_scan_kernel(const int* __restrict__ mask)
{
    const int qt = blockIdx.x, kt = blockIdx.y;
    const int tid = threadIdx.x;
    const int r = tid >> 1, h = tid & 1;
    const int* p = mask + (qt * 128 + r) * S_ + kt * 64 + h * 32;
    bool ok = true;
#pragma unroll
    for (int j = 0; j < 8; j++) {
        int4 v = *(const int4*)(p + j * 4);
        ok &= (v.x != 0) & (v.y != 0) & (v.z != 0) & (v.w != 0);
    }
    const int all = __syncthreads_and((int)ok);
    if (tid == 0) g_mflag[qt * 32 + kt] = all;
}

// ---------------------------------------------------------------------------
// Flash attention with tf32 mma. One block: one (b,h), 128 q-rows.
// 8 warps; warp w owns q-rows w*16..w*16+15 (full row => warp-local softmax).
// Perm smem layout: p(c) = (c&3)*18 + (c>>2), row stride 72 =>
// every mma fragment load is an aligned float2 at the 256B/warp crossbar floor.
// ---------------------------------------------------------------------------
#define QS_N (128 * 72)
#define KS_N (64 * 72)
#define VT_N (64 * 72)
#define PS_N (128 * 72)
#define ATTN_SMEM_BYTES ((QS_N + KS_N + VT_N + PS_N) * 4)

__global__ __launch_bounds__(256) void attn_kernel(const int* __restrict__ mask)
{
    extern __shared__ __align__(16) float sm[];
    float* Qs = sm;
    float* Ks = Qs + QS_N;
    float* Vt = Ks + KS_N;
    float* Ps = Vt + VT_N;

    const int tid = threadIdx.x;
    const int lane = tid & 31, wid = tid >> 5;
    const int g = lane >> 2, tg = lane & 3;
    const int w16 = wid * 16;
    const int q0 = blockIdx.x * 128;
    const int bh = blockIdx.y;

    const float* Qg = g_q + bh * S_ * DK_;
    const float* Kg = g_k + bh * S_ * DK_;
    const float* Vg = g_v + bh * S_ * DK_;

    // Load Q tile (128x64) into perm layout, once.
    {
        const int r = tid >> 1, hf = tid & 1;
        const float* p = Qg + (q0 + r) * DK_ + hf * 32;
        float* dst = Qs + r * 72;
#pragma unroll
        for (int j = 0; j < 8; j++) {
            float4 v = *(const float4*)(p + j * 4);
            const int pg = hf * 8 + j;   // (c>>2)
            dst[pg] = v.x; dst[18 + pg] = v.y; dst[36 + pg] = v.z; dst[54 + pg] = v.w;
        }
    }

    float mrow0 = -1e30f, mrow1 = -1e30f;
    float lrow0 = 0.0f, lrow1 = 0.0f;
    float o[8][4];
#pragma unroll
    for (int nt = 0; nt < 8; nt++)
#pragma unroll
        for (int i = 0; i < 4; i++) o[nt][i] = 0.0f;

    const int pb = ((tg * 2) & 3) * 18 + (tg >> 1);  // perm base for P writes
    const int fA = tg * 18;                          // perm col base for frag loads

    for (int kt = 0; kt < S_ / 64; kt++) {
        const int k0 = kt * 64;
        __syncthreads();
        // Load K (perm) and V (transposed perm) tiles
        {
            const int r = tid >> 2, qd = tid & 3;
            const float* pk = Kg + (k0 + r) * DK_ + qd * 16;
            float* kd = Ks + r * 72;
#pragma unroll
            for (int j = 0; j < 4; j++) {
                float4 v = *(const float4*)(pk + j * 4);
                const int pg = qd * 4 + j;
                kd[pg] = v.x; kd[18 + pg] = v.y; kd[36 + pg] = v.z; kd[54 + pg] = v.w;
            }
            const float* pv = Vg + (k0 + r) * DK_ + qd * 16;
            const int pkr = (r & 3) * 18 + (r >> 2);
#pragma unroll
            for (int j = 0; j < 4; j++) {
                float4 v = *(const float4*)(pv + j * 4);
                const int n = qd * 16 + j * 4;
                Vt[(n + 0) * 72 + pkr] = v.x;
                Vt[(n + 1) * 72 + pkr] = v.y;
                Vt[(n + 2) * 72 + pkr] = v.z;
                Vt[(n + 3) * 72 + pkr] = v.w;
            }
        }
        __syncthreads();

        // S = Qs @ Ks^T  (warp: 16x64)
        float s[8][4];
#pragma unroll
        for (int nt = 0; nt < 8; nt++)
#pragma unroll
            for (int i = 0; i < 4; i++) s[nt][i] = 0.0f;

#pragma unroll
        for (int kk = 0; kk < 8; kk++) {
            const float2 aA = *(const float2*)&Qs[(w16 + g) * 72 + fA + kk * 2];
            const float2 aB = *(const float2*)&Qs[(w16 + 8 + g) * 72 + fA + kk * 2];
#pragma unroll
            for (int nt = 0; nt < 8; nt++) {
                const float2 bv = *(const float2*)&Ks[(nt * 8 + g) * 72 + fA + kk * 2];
                mma8(s[nt], aA.x, aB.x, aA.y, aB.y, bv.x, bv.y);
            }
        }

        // Mask (rare path; flag precomputed)
        if (!g_mflag[blockIdx.x * 32 + kt]) {
            const int* mp0 = mask + (q0 + w16 + g) * S_ + k0 + tg * 2;
            const int* mp1 = mp0 + 8 * S_;
#pragma unroll
            for (int nt = 0; nt < 8; nt++) {
                const int2 m0v = *(const int2*)(mp0 + nt * 8);
                const int2 m1v = *(const int2*)(mp1 + nt * 8);
                if (m0v.x == 0) s[nt][0] = -1e9f;
                if (m0v.y == 0) s[nt][1] = -1e9f;
                if (m1v.x == 0) s[nt][2] = -1e9f;
                if (m1v.y == 0) s[nt][3] = -1e9f;
            }
        }

        // Online softmax (rows g and g+8; reduce across quad lanes tg)
        float mx0 = -1e30f, mx1 = -1e30f;
#pragma unroll
        for (int nt = 0; nt < 8; nt++) {
            mx0 = fmaxf(mx0, fmaxf(s[nt][0], s[nt][1]));
            mx1 = fmaxf(mx1, fmaxf(s[nt][2], s[nt][3]));
        }
        mx0 = fmaxf(mx0, __shfl_xor_sync(0xffffffffu, mx0, 1));
        mx0 = fmaxf(mx0, __shfl_xor_sync(0xffffffffu, mx0, 2));
        mx1 = fmaxf(mx1, __shfl_xor_sync(0xffffffffu, mx1, 1));
        mx1 = fmaxf(mx1, __shfl_xor_sync(0xffffffffu, mx1, 2));
        const float mn0 = fmaxf(mrow0, mx0);
        const float mn1 = fmaxf(mrow1, mx1);
        const float al0 = __expf(mrow0 - mn0);
        const float al1 = __expf(mrow1 - mn1);
        mrow0 = mn0; mrow1 = mn1;

        float sum0 = 0.0f, sum1 = 0.0f;
        float* P0 = &Ps[(w16 + g) * 72 + pb];
        float* P1 = &Ps[(w16 + 8 + g) * 72 + pb];
#pragma unroll
        for (int nt = 0; nt < 8; nt++) {
            const float p0 = __expf(s[nt][0] - mn0);
            const float p1 = __expf(s[nt][1] - mn0);
            const float p2 = __expf(s[nt][2] - mn1);
            const float p3 = __expf(s[nt][3] - mn1);
            sum0 += p0 + p1;
            sum1 += p2 + p3;
            P0[nt * 2] = to_tf32(p0);
            P0[nt * 2 + 18] = to_tf32(p1);
            P1[nt * 2] = to_tf32(p2);
            P1[nt * 2 + 18] = to_tf32(p3);
            o[nt][0] *= al0; o[nt][1] *= al0;
            o[nt][2] *= al1; o[nt][3] *= al1;
        }
        sum0 += __shfl_xor_sync(0xffffffffu, sum0, 1);
        sum0 += __shfl_xor_sync(0xffffffffu, sum0, 2);
        sum1 += __shfl_xor_sync(0xffffffffu, sum1, 1);
        sum1 += __shfl_xor_sync(0xffffffffu, sum1, 2);
        lrow0 = lrow0 * al0 + sum0;
        lrow1 = lrow1 * al1 + sum1;
        __syncwarp();

        // O += P @ V  (warp: 16x64)
#pragma unroll
        for (int kk = 0; kk < 8; kk++) {
            const float2 aA = *(const float2*)&Ps[(w16 + g) * 72 + fA + kk * 2];
            const float2 aB = *(const float2*)&Ps[(w16 + 8 + g) * 72 + fA + kk * 2];
#pragma unroll
            for (int nt = 0; nt < 8; nt++) {
                const float2 bv = *(const float2*)&Vt[(nt * 8 + g) * 72 + fA + kk * 2];
                mma8(o[nt], aA.x, aB.x, aA.y, aB.y, bv.x, bv.y);
            }
        }
    }

    // Normalize and store to [B,S,D]
    const float inv0 = 1.0f / lrow0;
    const float inv1 = 1.0f / lrow1;
    const int bb = bh >> 4, h = bh & 15;
    const int r0 = q0 + w16 + g;
    float* O0 = &g_x[(bb * S_ + r0) * D_ + h * DK_ + tg * 2];
    float* O1 = O0 + 8 * D_;
#pragma unroll
    for (int nt = 0; nt < 8; nt++) {
        *(float2*)(O0 + nt * 8) = make_float2(o[nt][0] * inv0, o[nt][1] * inv0);
        *(float2*)(O1 + nt * 8) = make_float2(o[nt][2] * inv1, o[nt][3] * inv1);
    }
}

// ---------------------------------------------------------------------------
extern "C" void kernel_launch(void* const* d_in, const int* in_sizes, int n_in,
                              void* d_out, int out_size)
{
    (void)in_sizes; (void)n_in; (void)out_size;
    const float* q    = (const float*)d_in[0];
    const float* k    = (const float*)d_in[1];
    const float* v    = (const float*)d_in[2];
    const int*   mask = (const int*)d_in[3];
    const float* wq   = (const float*)d_in[4];
    const float* bq   = (const float*)d_in[5];
    const float* wk   = (const float*)d_in[6];
    const float* bk   = (const float*)d_in[7];
    const float* wv   = (const float*)d_in[8];
    const float* bv   = (const float*)d_in[9];
    const float* wo   = (const float*)d_in[10];
    const float* bo   = (const float*)d_in[11];
    float* out = (float*)d_out;

    // QKV projections (tensor-core tf32)
    dim3 gqkv(D_ / 128, M_ / 128, 3);
    qkv_kernel<<<gqkv, 256>>>(q, k, v, wq, bq, wk, bk, wv, bv);

    // Mask prescan (tiny; overlaps nothing but is ~10us worst case)
    dim3 gms(16, 32);
    mask_scan_kernel<<<gms, 256>>>(mask);

    // Attention
    cudaFuncSetAttribute(attn_kernel, cudaFuncAttributeMaxDynamicSharedMemorySize,
                         ATTN_SMEM_BYTES);
    dim3 gattn(S_ / 128, B_ * H_);
    attn_kernel<<<gattn, 256, ATTN_SMEM_BYTES>>>(mask);

    // Output projection
    dim3 gop(D_ / 128, M_ / 128);
    oproj_kernel<<<gop, 256>>>(wo, bo, out);
}